// round 1
// baseline (speedup 1.0000x reference)
#include <cuda_runtime.h>
#include <cuda_bf16.h>
#include <cstdint>

// Problem constants
#define BS      4096
#define Z_DIM   512
#define HID     1024
#define Z_IN    128
#define N_STEP  32
#define OUT_DIM 3
#define G3      (3*HID)        // 3072
#define X_DIM   (OUT_DIM+Z_IN) // 131

// Scratch (device globals — no allocation allowed)
__device__ float g_h[BS * HID];
__device__ float g_gi[BS * G3];
__device__ float g_gh[BS * G3];
__device__ float g_zin[BS * Z_IN];
__device__ float g_token[BS * OUT_DIM];
__device__ float g_tokw[G3 * OUT_DIM];

// ---------------------------------------------------------------------------
// helpers
// ---------------------------------------------------------------------------
__device__ __forceinline__ float to_tf32(float x) {
    uint32_t r;
    asm("cvt.rna.tf32.f32 %0, %1;" : "=r"(r) : "f"(x));
    return __uint_as_float(r);
}

__device__ __forceinline__ void mma_m16n8k8_tf32(float* c, const uint32_t* a, const uint32_t* b) {
    asm volatile(
        "mma.sync.aligned.m16n8k8.row.col.f32.tf32.tf32.f32 "
        "{%0,%1,%2,%3}, {%4,%5,%6,%7}, {%8,%9}, {%0,%1,%2,%3};\n"
        : "+f"(c[0]), "+f"(c[1]), "+f"(c[2]), "+f"(c[3])
        : "r"(a[0]), "r"(a[1]), "r"(a[2]), "r"(a[3]),
          "r"(b[0]), "r"(b[1]));
}

__device__ __forceinline__ float sigmoidf(float x) {
    return 1.0f / (1.0f + expf(-x));
}

// ---------------------------------------------------------------------------
// Generic tf32 GEMM:  C[M,N] = A[M,K](lda) * B[N,K](ldb)^T + bias[N]
// Both A and B are K-contiguous (row-major). BM=128, BN=128, BK=32, 256 thr.
// ---------------------------------------------------------------------------
#define BM 128
#define BN 128
#define BK 32

__global__ void __launch_bounds__(256)
gemm_tf32(const float* __restrict__ A, int lda,
          const float* __restrict__ B, int ldb,
          const float* __restrict__ bias,
          float* __restrict__ C,
          int M, int N, int K)
{
    __shared__ float As[BM][BK + 4];   // +4 pad: bank = (4*row + col) % 32, conflict-free frags
    __shared__ float Bs[BN][BK + 4];

    const int m0   = blockIdx.y * BM;
    const int n0   = blockIdx.x * BN;
    const int tid  = threadIdx.x;
    const int lane = tid & 31;
    const int warp = tid >> 5;
    const int wm   = warp & 3;   // 4 warps along M
    const int wn   = warp >> 2;  // 2 warps along N
    const int gid  = lane >> 2;  // 0..7
    const int l4   = lane & 3;   // 0..3

    float acc[2][8][4];
#pragma unroll
    for (int mt = 0; mt < 2; mt++)
#pragma unroll
        for (int nt = 0; nt < 8; nt++)
#pragma unroll
            for (int i = 0; i < 4; i++) acc[mt][nt][i] = 0.0f;

    for (int kt = 0; kt < K; kt += BK) {
        // load + tf32-round A tile (128x32) and B tile (128x32)
#pragma unroll
        for (int i = 0; i < 16; i++) {
            int e = tid + i * 256;
            int r = e >> 5, c = e & 31;
            As[r][c] = to_tf32(A[(size_t)(m0 + r) * lda + kt + c]);
        }
#pragma unroll
        for (int i = 0; i < 16; i++) {
            int e = tid + i * 256;
            int r = e >> 5, c = e & 31;
            Bs[r][c] = to_tf32(B[(size_t)(n0 + r) * ldb + kt + c]);
        }
        __syncthreads();

#pragma unroll
        for (int kk = 0; kk < BK; kk += 8) {
            uint32_t af[2][4], bf[8][2];
#pragma unroll
            for (int mt = 0; mt < 2; mt++) {
                int rb = wm * 32 + mt * 16 + gid;
                af[mt][0] = __float_as_uint(As[rb    ][kk + l4    ]);
                af[mt][1] = __float_as_uint(As[rb + 8][kk + l4    ]);
                af[mt][2] = __float_as_uint(As[rb    ][kk + l4 + 4]);
                af[mt][3] = __float_as_uint(As[rb + 8][kk + l4 + 4]);
            }
#pragma unroll
            for (int nt = 0; nt < 8; nt++) {
                int rb = wn * 64 + nt * 8 + gid;
                bf[nt][0] = __float_as_uint(Bs[rb][kk + l4    ]);
                bf[nt][1] = __float_as_uint(Bs[rb][kk + l4 + 4]);
            }
#pragma unroll
            for (int mt = 0; mt < 2; mt++)
#pragma unroll
                for (int nt = 0; nt < 8; nt++)
                    mma_m16n8k8_tf32(acc[mt][nt], af[mt], bf[nt]);
        }
        __syncthreads();
    }

    // epilogue: C += bias, row-major stores (float2 per fragment row)
#pragma unroll
    for (int mt = 0; mt < 2; mt++) {
#pragma unroll
        for (int nt = 0; nt < 8; nt++) {
            int row = m0 + wm * 32 + mt * 16 + gid;
            int col = n0 + wn * 64 + nt * 8 + l4 * 2;
            float b0 = bias[col], b1 = bias[col + 1];
            float* p0 = &C[(size_t)row * N + col];
            float* p1 = &C[(size_t)(row + 8) * N + col];
            p0[0] = acc[mt][nt][0] + b0;
            p0[1] = acc[mt][nt][1] + b1;
            p1[0] = acc[mt][nt][2] + b0;
            p1[1] = acc[mt][nt][3] + b1;
        }
    }
}

// ---------------------------------------------------------------------------
// Setup: compact token-weight slice W_ih[:, 0:3] and broadcast init token
// ---------------------------------------------------------------------------
__global__ void setup_kernel(const float* __restrict__ W_ih,
                             const float* __restrict__ init_input)
{
    int i = blockIdx.x * blockDim.x + threadIdx.x;
    if (i < G3 * OUT_DIM)
        g_tokw[i] = W_ih[(i / OUT_DIM) * X_DIM + (i % OUT_DIM)];
    if (i < BS * OUT_DIM)
        g_token[i] = init_input[i % OUT_DIM];
}

// ---------------------------------------------------------------------------
// Fused GRU gate + hidden update + 3-wide output head. One block per row.
// gi (with b_ih) precomputed once; gh (with b_hh) produced by GEMM this step.
// ---------------------------------------------------------------------------
__global__ void __launch_bounds__(256)
gru_step_kernel(const float* __restrict__ W_out,
                const float* __restrict__ b_out,
                float* __restrict__ recon,
                int t)
{
    const int row = blockIdx.x;
    const int tid = threadIdx.x;
    const int lane = tid & 31;
    const int warp = tid >> 5;

    __shared__ float tok[3];
    __shared__ float red[3][8];

    if (tid < 3) tok[tid] = g_token[row * 3 + tid];
    __syncthreads();
    const float t0 = tok[0], t1 = tok[1], t2 = tok[2];

    const float* gi = g_gi + (size_t)row * G3;
    const float* gh = g_gh + (size_t)row * G3;
    float*       h  = g_h  + (size_t)row * HID;

    float o0 = 0.f, o1 = 0.f, o2 = 0.f;

#pragma unroll
    for (int s = 0; s < HID / 256; s++) {
        int u = tid + s * 256;
        const float* wr = &g_tokw[(size_t)u * 3];
        const float* wu = &g_tokw[(size_t)(HID + u) * 3];
        const float* wn = &g_tokw[(size_t)(2 * HID + u) * 3];

        float ir = gi[u]           + t0 * wr[0] + t1 * wr[1] + t2 * wr[2];
        float iu = gi[HID + u]     + t0 * wu[0] + t1 * wu[1] + t2 * wu[2];
        float in_ = gi[2 * HID + u] + t0 * wn[0] + t1 * wn[1] + t2 * wn[2];

        float hr = gh[u], hu = gh[HID + u], hn = gh[2 * HID + u];

        float r  = sigmoidf(ir + hr);
        float uu = sigmoidf(iu + hu);
        float n  = tanhf(in_ + r * hn);
        float hold = h[u];
        float hnew = (1.0f - uu) * n + uu * hold;
        h[u] = hnew;

        o0 += hnew * W_out[u];
        o1 += hnew * W_out[HID + u];
        o2 += hnew * W_out[2 * HID + u];
    }

    // block reduction of the 3 output partials
#pragma unroll
    for (int off = 16; off > 0; off >>= 1) {
        o0 += __shfl_down_sync(0xffffffffu, o0, off);
        o1 += __shfl_down_sync(0xffffffffu, o1, off);
        o2 += __shfl_down_sync(0xffffffffu, o2, off);
    }
    if (lane == 0) { red[0][warp] = o0; red[1][warp] = o1; red[2][warp] = o2; }
    __syncthreads();

    if (tid == 0) {
        float s0 = 0.f, s1 = 0.f, s2 = 0.f;
#pragma unroll
        for (int w = 0; w < 8; w++) { s0 += red[0][w]; s1 += red[1][w]; s2 += red[2][w]; }
        float bass    = sigmoidf(s0 + b_out[0]);
        float rhy_int = s1 + b_out[1];
        float rhy     = sigmoidf(s2 + b_out[2]);

        float* rc = recon + (size_t)row * (N_STEP * OUT_DIM) + t * OUT_DIM;
        rc[0] = bass; rc[1] = rhy_int; rc[2] = rhy;

        g_token[row * 3 + 0] = bass;
        g_token[row * 3 + 1] = rhy_int;
        g_token[row * 3 + 2] = (rhy > 0.5f) ? 1.0f : 0.0f;
    }
}

// ---------------------------------------------------------------------------
// kernel_launch
// inputs: 0 z, 1 inference, 2 tfr, 3 W_zh, 4 b_zh, 5 W_zi, 6 b_zi,
//         7 W_ih, 8 b_ih, 9 W_hh, 10 b_hh, 11 W_out, 12 b_out, 13 init_input
// ---------------------------------------------------------------------------
extern "C" void kernel_launch(void* const* d_in, const int* in_sizes, int n_in,
                              void* d_out, int out_size)
{
    (void)in_sizes; (void)n_in; (void)out_size;

    const float* z      = (const float*)d_in[0];
    const float* W_zh   = (const float*)d_in[3];
    const float* b_zh   = (const float*)d_in[4];
    const float* W_zi   = (const float*)d_in[5];
    const float* b_zi   = (const float*)d_in[6];
    const float* W_ih   = (const float*)d_in[7];
    const float* b_ih   = (const float*)d_in[8];
    const float* W_hh   = (const float*)d_in[9];
    const float* b_hh   = (const float*)d_in[10];
    const float* W_out  = (const float*)d_in[11];
    const float* b_out  = (const float*)d_in[12];
    const float* initin = (const float*)d_in[13];
    float* recon = (float*)d_out;

    float *p_h, *p_gi, *p_gh, *p_zin;
    cudaGetSymbolAddress((void**)&p_h,   g_h);
    cudaGetSymbolAddress((void**)&p_gi,  g_gi);
    cudaGetSymbolAddress((void**)&p_gh,  g_gh);
    cudaGetSymbolAddress((void**)&p_zin, g_zin);

    // setup: token init + compact token weights
    setup_kernel<<<48, 256>>>(W_ih, initin);

    // h0 = z @ W_zh^T + b_zh       (M=4096, N=1024, K=512)
    gemm_tf32<<<dim3(HID / BN, BS / BM), 256>>>(z, Z_DIM, W_zh, Z_DIM, b_zh, p_h, BS, HID, Z_DIM);
    // z_in = z @ W_zi^T + b_zi     (M=4096, N=128, K=512)
    gemm_tf32<<<dim3(Z_IN / BN, BS / BM), 256>>>(z, Z_DIM, W_zi, Z_DIM, b_zi, p_zin, BS, Z_IN, Z_DIM);
    // gi = z_in @ W_ih[:,3:]^T + b_ih   (M=4096, N=3072, K=128; B is strided ldb=131, offset 3)
    gemm_tf32<<<dim3(G3 / BN, BS / BM), 256>>>(p_zin, Z_IN, W_ih + OUT_DIM, X_DIM, b_ih, p_gi, BS, G3, Z_IN);

    for (int t = 0; t < N_STEP; t++) {
        // gh = h @ W_hh^T + b_hh   (M=4096, N=3072, K=1024) — the hot GEMM
        gemm_tf32<<<dim3(G3 / BN, BS / BM), 256>>>(p_h, HID, W_hh, HID, b_hh, p_gh, BS, G3, HID);
        // fused GRU update + output head
        gru_step_kernel<<<BS, 256>>>(W_out, b_out, recon, t);
    }
}

// round 4
// speedup vs baseline: 2.5126x; 2.5126x over previous
#include <cuda_runtime.h>
#include <cuda_bf16.h>
#include <cstdint>

// Problem constants
#define BS      4096
#define Z_DIM   512
#define HID     1024
#define Z_IN    128
#define N_STEP  32
#define OUT_DIM 3
#define G3      (3*HID)        // 3072
#define X_DIM   (OUT_DIM+Z_IN) // 131

// Scratch (device globals — no allocation allowed)
__device__ float g_h[BS * HID];        // exact hidden state
__device__ float g_htf_a[BS * HID];    // tf32-rounded hidden, ping
__device__ float g_htf_b[BS * HID];    // tf32-rounded hidden, pong
__device__ float g_gi[BS * G3];        // z_in part of input gates (+b_ih)
__device__ float g_zin[BS * Z_IN];
__device__ float g_token[BS * OUT_DIM];
__device__ float g_tokw[G3 * OUT_DIM]; // W_ih[:, 0:3] compacted
__device__ float g_Wt[G3 * HID];       // tf32-rounded W_hh

// ---------------------------------------------------------------------------
// helpers
// ---------------------------------------------------------------------------
__device__ __forceinline__ float to_tf32(float x) {
    uint32_t r;
    asm("cvt.rna.tf32.f32 %0, %1;" : "=r"(r) : "f"(x));
    return __uint_as_float(r);
}

__device__ __forceinline__ void mma_m16n8k8_tf32(float* c, const uint32_t* a, const uint32_t* b) {
    asm volatile(
        "mma.sync.aligned.m16n8k8.row.col.f32.tf32.tf32.f32 "
        "{%0,%1,%2,%3}, {%4,%5,%6,%7}, {%8,%9}, {%0,%1,%2,%3};\n"
        : "+f"(c[0]), "+f"(c[1]), "+f"(c[2]), "+f"(c[3])
        : "r"(a[0]), "r"(a[1]), "r"(a[2]), "r"(a[3]),
          "r"(b[0]), "r"(b[1]));
}

// EXACT activations (match round-1 passing numerics)
__device__ __forceinline__ float sigmoidf(float x) {
    return 1.0f / (1.0f + expf(-x));
}

__device__ __forceinline__ void cp16(uint32_t dst, const float* src) {
    asm volatile("cp.async.cg.shared.global [%0], [%1], 16;" :: "r"(dst), "l"(src));
}
#define CP_COMMIT() asm volatile("cp.async.commit_group;")
#define CP_WAIT(n)  asm volatile("cp.async.wait_group %0;" :: "n"(n))

// ---------------------------------------------------------------------------
// Prologue GEMM: C[M,N] = A[M,K](lda) * B[N,K](ldb)^T + bias[N]
// ---------------------------------------------------------------------------
#define BM 128
#define BN 128
#define BK 32

__global__ void __launch_bounds__(256)
gemm_tf32(const float* __restrict__ A, int lda,
          const float* __restrict__ B, int ldb,
          const float* __restrict__ bias,
          float* __restrict__ C,
          int M, int N, int K)
{
    __shared__ float As[BM][BK + 4];
    __shared__ float Bs[BN][BK + 4];

    const int m0   = blockIdx.y * BM;
    const int n0   = blockIdx.x * BN;
    const int tid  = threadIdx.x;
    const int lane = tid & 31;
    const int warp = tid >> 5;
    const int wm   = warp & 3;
    const int wn   = warp >> 2;
    const int gid  = lane >> 2;
    const int l4   = lane & 3;

    float acc[2][8][4];
#pragma unroll
    for (int mt = 0; mt < 2; mt++)
#pragma unroll
        for (int nt = 0; nt < 8; nt++)
#pragma unroll
            for (int i = 0; i < 4; i++) acc[mt][nt][i] = 0.0f;

    for (int kt = 0; kt < K; kt += BK) {
#pragma unroll
        for (int i = 0; i < 16; i++) {
            int e = tid + i * 256;
            int r = e >> 5, c = e & 31;
            As[r][c] = to_tf32(A[(size_t)(m0 + r) * lda + kt + c]);
        }
#pragma unroll
        for (int i = 0; i < 16; i++) {
            int e = tid + i * 256;
            int r = e >> 5, c = e & 31;
            Bs[r][c] = to_tf32(B[(size_t)(n0 + r) * ldb + kt + c]);
        }
        __syncthreads();

#pragma unroll
        for (int kk = 0; kk < BK; kk += 8) {
            uint32_t af[2][4], bf[8][2];
#pragma unroll
            for (int mt = 0; mt < 2; mt++) {
                int rb = wm * 32 + mt * 16 + gid;
                af[mt][0] = __float_as_uint(As[rb    ][kk + l4    ]);
                af[mt][1] = __float_as_uint(As[rb + 8][kk + l4    ]);
                af[mt][2] = __float_as_uint(As[rb    ][kk + l4 + 4]);
                af[mt][3] = __float_as_uint(As[rb + 8][kk + l4 + 4]);
            }
#pragma unroll
            for (int nt = 0; nt < 8; nt++) {
                int rb = wn * 64 + nt * 8 + gid;
                bf[nt][0] = __float_as_uint(Bs[rb][kk + l4    ]);
                bf[nt][1] = __float_as_uint(Bs[rb][kk + l4 + 4]);
            }
#pragma unroll
            for (int mt = 0; mt < 2; mt++)
#pragma unroll
                for (int nt = 0; nt < 8; nt++)
                    mma_m16n8k8_tf32(acc[mt][nt], af[mt], bf[nt]);
        }
        __syncthreads();
    }

#pragma unroll
    for (int mt = 0; mt < 2; mt++) {
#pragma unroll
        for (int nt = 0; nt < 8; nt++) {
            int row = m0 + wm * 32 + mt * 16 + gid;
            int col = n0 + wn * 64 + nt * 8 + l4 * 2;
            float b0 = bias[col], b1 = bias[col + 1];
            float* p0 = &C[(size_t)row * N + col];
            float* p1 = &C[(size_t)(row + 8) * N + col];
            p0[0] = acc[mt][nt][0] + b0;
            p0[1] = acc[mt][nt][1] + b1;
            p1[0] = acc[mt][nt][2] + b0;
            p1[1] = acc[mt][nt][3] + b1;
        }
    }
}

// ---------------------------------------------------------------------------
// Setup + converts
// ---------------------------------------------------------------------------
__global__ void setup_kernel(const float* __restrict__ W_ih,
                             const float* __restrict__ init_input)
{
    int i = blockIdx.x * blockDim.x + threadIdx.x;
    if (i < G3 * OUT_DIM)
        g_tokw[i] = W_ih[(i / OUT_DIM) * X_DIM + (i % OUT_DIM)];
    if (i < BS * OUT_DIM)
        g_token[i] = init_input[i % OUT_DIM];
}

__global__ void conv_w_kernel(const float* __restrict__ W_hh) {
    int i = blockIdx.x * blockDim.x + threadIdx.x;
    if (i < G3 * HID) g_Wt[i] = to_tf32(W_hh[i]);
}
__global__ void conv_h_kernel() {
    int i = blockIdx.x * blockDim.x + threadIdx.x;
    if (i < BS * HID) g_htf_a[i] = to_tf32(g_h[i]);
}

// ---------------------------------------------------------------------------
// Fused step kernel: gh = h @ W_hh^T (3 gates) fused with GRU update.
// CTA tile: 128 rows x 64 units x 3 gates. 256 threads, cp.async 2-stage.
// A operand read from hsrc (tf32 buffer t); epilogue writes hdst (buffer t+1)
// — double buffering removes the cross-CTA read/write race on the h state.
// ---------------------------------------------------------------------------
#define FBM 128
#define FBU 64
#define FBN 192
#define FBK 32
#define FST 36                      // row stride in floats (BK + 4 pad)
#define A_STG_F (FBM*FST)           // 4608 floats per stage
#define B_STG_F (FBN*FST)           // 6912 floats per stage
#define SB_OFF_F (2*A_STG_F)        // 9216
#define EXTRA_OFF_F (SB_OFF_F + 2*B_STG_F)   // 23040
#define FUSED_SMEM_BYTES ((EXTRA_OFF_F + FBM*3 + FBN*3 + FBN) * 4)  // 96768

__global__ void __launch_bounds__(256)
fused_step(const float* __restrict__ hsrc,   // tf32 h(t), read-only
           float* __restrict__ hdst,         // tf32 h(t+1), write-only
           const float* __restrict__ b_hh)
{
    extern __shared__ float smem[];
    float* s_tok = smem + EXTRA_OFF_F;          // [FBM*3]
    float* s_tw  = s_tok + FBM * 3;             // [(g*64+u)*3 + j]
    float* s_bh  = s_tw + FBN * 3;              // [g*64+u]

    const int n0  = blockIdx.x * FBU;
    const int m0  = blockIdx.y * FBM;
    const int tid = threadIdx.x;
    const int lane = tid & 31;
    const int warp = tid >> 5;
    const int wm = warp & 3;        // 4 warps along M (32 rows each)
    const int wn = warp >> 2;       // 2 warps along N (32 units each)
    const int gid = lane >> 2;
    const int l4  = lane & 3;

    // stage constant epilogue data
    for (int e = tid; e < FBM * 3; e += 256) s_tok[e] = g_token[m0 * 3 + e];
    for (int e = tid; e < FBN * 3; e += 256) {
        int rg = e / 3, j = e - rg * 3;
        int g = rg >> 6, u = rg & 63;
        s_tw[e] = g_tokw[((size_t)g * HID + n0 + u) * 3 + j];
    }
    if (tid < FBN) s_bh[tid] = b_hh[(tid >> 6) * HID + n0 + (tid & 63)];

    // per-thread cp.async coordinates
    uint32_t sbase = (uint32_t)__cvta_generic_to_shared(smem);
    uint32_t aoffs[4]; const float* agp[4];
#pragma unroll
    for (int i = 0; i < 4; i++) {
        int c = tid + i * 256;
        int r = c >> 3, j = c & 7;
        aoffs[i] = sbase + (uint32_t)(r * FST + j * 4) * 4u;
        agp[i]   = hsrc + (size_t)(m0 + r) * HID + j * 4;
    }
    uint32_t boffs[6]; const float* bgp[6];
#pragma unroll
    for (int i = 0; i < 6; i++) {
        int c = tid + i * 256;
        int r = c >> 3, j = c & 7;
        boffs[i] = sbase + (uint32_t)(SB_OFF_F + r * FST + j * 4) * 4u;
        bgp[i]   = g_Wt + (size_t)((r >> 6) * HID + n0 + (r & 63)) * HID + j * 4;
    }

    float acc[3][2][4][4];
#pragma unroll
    for (int g = 0; g < 3; g++)
#pragma unroll
        for (int mt = 0; mt < 2; mt++)
#pragma unroll
            for (int nt = 0; nt < 4; nt++)
#pragma unroll
                for (int i = 0; i < 4; i++) acc[g][mt][nt][i] = 0.0f;

    auto issue = [&](int st, int kt) {
#pragma unroll
        for (int i = 0; i < 4; i++) cp16(aoffs[i] + (uint32_t)st * (A_STG_F * 4), agp[i] + kt);
#pragma unroll
        for (int i = 0; i < 6; i++) cp16(boffs[i] + (uint32_t)st * (B_STG_F * 4), bgp[i] + kt);
    };

    const int NKT = HID / FBK;   // 32
    issue(0, 0); CP_COMMIT();

    for (int it = 0; it < NKT; ++it) {
        if (it + 1 < NKT) { issue((it + 1) & 1, (it + 1) * FBK); CP_COMMIT(); CP_WAIT(1); }
        else              { CP_WAIT(0); }
        __syncthreads();

        const float* Af = smem + (it & 1) * A_STG_F;
        const float* Bf = smem + SB_OFF_F + (it & 1) * B_STG_F;

#pragma unroll
        for (int kk = 0; kk < FBK; kk += 8) {
            uint32_t a[2][4];
#pragma unroll
            for (int mt = 0; mt < 2; mt++) {
                int rb = wm * 32 + mt * 16 + gid;
                a[mt][0] = __float_as_uint(Af[rb * FST + kk + l4]);
                a[mt][1] = __float_as_uint(Af[(rb + 8) * FST + kk + l4]);
                a[mt][2] = __float_as_uint(Af[rb * FST + kk + l4 + 4]);
                a[mt][3] = __float_as_uint(Af[(rb + 8) * FST + kk + l4 + 4]);
            }
#pragma unroll
            for (int g = 0; g < 3; g++) {
#pragma unroll
                for (int nt = 0; nt < 4; nt++) {
                    int rb = g * 64 + wn * 32 + nt * 8 + gid;
                    uint32_t b[2];
                    b[0] = __float_as_uint(Bf[rb * FST + kk + l4]);
                    b[1] = __float_as_uint(Bf[rb * FST + kk + l4 + 4]);
                    mma_m16n8k8_tf32(acc[g][0][nt], a[0], b);
                    mma_m16n8k8_tf32(acc[g][1][nt], a[1], b);
                }
            }
        }
        __syncthreads();
    }

    // ---- epilogue: GRU update in-register (exact activations) ----
#pragma unroll
    for (int mt = 0; mt < 2; mt++) {
#pragma unroll
        for (int rs = 0; rs < 2; rs++) {
            int rloc = wm * 32 + mt * 16 + gid + rs * 8;
            int grow = m0 + rloc;
            float t0 = s_tok[rloc * 3 + 0];
            float t1 = s_tok[rloc * 3 + 1];
            float t2 = s_tok[rloc * 3 + 2];
            const float* gi = g_gi + (size_t)grow * G3;
            float* hrow  = g_h  + (size_t)grow * HID;
            float* hfrow = hdst + (size_t)grow * HID;
#pragma unroll
            for (int nt = 0; nt < 4; nt++) {
                int ul = wn * 32 + nt * 8 + l4 * 2;   // local unit (even)
                int gu = n0 + ul;
                float2 gr  = *(const float2*)(gi + gu);
                float2 gu2 = *(const float2*)(gi + HID + gu);
                float2 gn  = *(const float2*)(gi + 2 * HID + gu);
                float2 h2  = *(const float2*)(hrow + gu);

                float hn_out[2];
#pragma unroll
                for (int c = 0; c < 2; c++) {
                    int u = ul + c;
                    float acc_r = acc[0][mt][nt][rs * 2 + c];
                    float acc_u = acc[1][mt][nt][rs * 2 + c];
                    float acc_n = acc[2][mt][nt][rs * 2 + c];
                    float gi_r = (c ? gr.y  : gr.x);
                    float gi_u = (c ? gu2.y : gu2.x);
                    float gi_n = (c ? gn.y  : gn.x);
                    float hold = (c ? h2.y  : h2.x);

                    float ir = gi_r + t0 * s_tw[(0 * 64 + u) * 3 + 0]
                                    + t1 * s_tw[(0 * 64 + u) * 3 + 1]
                                    + t2 * s_tw[(0 * 64 + u) * 3 + 2];
                    float iu = gi_u + t0 * s_tw[(1 * 64 + u) * 3 + 0]
                                    + t1 * s_tw[(1 * 64 + u) * 3 + 1]
                                    + t2 * s_tw[(1 * 64 + u) * 3 + 2];
                    float in_ = gi_n + t0 * s_tw[(2 * 64 + u) * 3 + 0]
                                     + t1 * s_tw[(2 * 64 + u) * 3 + 1]
                                     + t2 * s_tw[(2 * 64 + u) * 3 + 2];

                    float hr = acc_r + s_bh[u];
                    float hu = acc_u + s_bh[64 + u];
                    float hn = acc_n + s_bh[128 + u];

                    float r  = sigmoidf(ir + hr);
                    float uu = sigmoidf(iu + hu);
                    float n  = tanhf(in_ + r * hn);
                    hn_out[c] = (1.0f - uu) * n + uu * hold;
                }
                *(float2*)(hrow + gu)  = make_float2(hn_out[0], hn_out[1]);
                *(float2*)(hfrow + gu) = make_float2(to_tf32(hn_out[0]), to_tf32(hn_out[1]));
            }
        }
    }
}

// ---------------------------------------------------------------------------
// Output head: o = h_new @ W_out^T + b_out; recon + next token. 1 block/row.
// ---------------------------------------------------------------------------
__global__ void __launch_bounds__(128)
out_head(const float* __restrict__ W_out,
         const float* __restrict__ b_out,
         float* __restrict__ recon,
         int t)
{
    const int row = blockIdx.x;
    const int tid = threadIdx.x;
    const int lane = tid & 31;
    const int warp = tid >> 5;
    __shared__ float red[3][4];

    const float* h = g_h + (size_t)row * HID;
    float s0 = 0.f, s1 = 0.f, s2 = 0.f;
#pragma unroll
    for (int i = 0; i < HID / 128; i++) {
        int u = tid + i * 128;
        float hv = h[u];
        s0 += hv * W_out[u];
        s1 += hv * W_out[HID + u];
        s2 += hv * W_out[2 * HID + u];
    }
#pragma unroll
    for (int off = 16; off > 0; off >>= 1) {
        s0 += __shfl_down_sync(0xffffffffu, s0, off);
        s1 += __shfl_down_sync(0xffffffffu, s1, off);
        s2 += __shfl_down_sync(0xffffffffu, s2, off);
    }
    if (lane == 0) { red[0][warp] = s0; red[1][warp] = s1; red[2][warp] = s2; }
    __syncthreads();
    if (tid == 0) {
        float a0 = red[0][0] + red[0][1] + red[0][2] + red[0][3];
        float a1 = red[1][0] + red[1][1] + red[1][2] + red[1][3];
        float a2 = red[2][0] + red[2][1] + red[2][2] + red[2][3];
        float bass    = sigmoidf(a0 + b_out[0]);
        float rhy_int = a1 + b_out[1];
        float rhy     = sigmoidf(a2 + b_out[2]);

        float* rc = recon + (size_t)row * (N_STEP * OUT_DIM) + t * OUT_DIM;
        rc[0] = bass; rc[1] = rhy_int; rc[2] = rhy;

        g_token[row * 3 + 0] = bass;
        g_token[row * 3 + 1] = rhy_int;
        g_token[row * 3 + 2] = (rhy > 0.5f) ? 1.0f : 0.0f;
    }
}

// ---------------------------------------------------------------------------
// kernel_launch
// inputs: 0 z, 1 inference, 2 tfr, 3 W_zh, 4 b_zh, 5 W_zi, 6 b_zi,
//         7 W_ih, 8 b_ih, 9 W_hh, 10 b_hh, 11 W_out, 12 b_out, 13 init_input
// ---------------------------------------------------------------------------
extern "C" void kernel_launch(void* const* d_in, const int* in_sizes, int n_in,
                              void* d_out, int out_size)
{
    (void)in_sizes; (void)n_in; (void)out_size;

    const float* z      = (const float*)d_in[0];
    const float* W_zh   = (const float*)d_in[3];
    const float* b_zh   = (const float*)d_in[4];
    const float* W_zi   = (const float*)d_in[5];
    const float* b_zi   = (const float*)d_in[6];
    const float* W_ih   = (const float*)d_in[7];
    const float* b_ih   = (const float*)d_in[8];
    const float* W_hh   = (const float*)d_in[9];
    const float* b_hh   = (const float*)d_in[10];
    const float* W_out  = (const float*)d_in[11];
    const float* b_out  = (const float*)d_in[12];
    const float* initin = (const float*)d_in[13];
    float* recon = (float*)d_out;

    float *p_h, *p_gi, *p_zin, *p_ha, *p_hb;
    cudaGetSymbolAddress((void**)&p_h,   g_h);
    cudaGetSymbolAddress((void**)&p_gi,  g_gi);
    cudaGetSymbolAddress((void**)&p_zin, g_zin);
    cudaGetSymbolAddress((void**)&p_ha,  g_htf_a);
    cudaGetSymbolAddress((void**)&p_hb,  g_htf_b);

    cudaFuncSetAttribute(fused_step, cudaFuncAttributeMaxDynamicSharedMemorySize,
                         FUSED_SMEM_BYTES);

    // setup + weight conversion
    setup_kernel<<<48, 256>>>(W_ih, initin);
    conv_w_kernel<<<(G3 * HID + 255) / 256, 256>>>(W_hh);

    // h0 = z @ W_zh^T + b_zh
    gemm_tf32<<<dim3(HID / BN, BS / BM), 256>>>(z, Z_DIM, W_zh, Z_DIM, b_zh, p_h, BS, HID, Z_DIM);
    // z_in = z @ W_zi^T + b_zi
    gemm_tf32<<<dim3(Z_IN / BN, BS / BM), 256>>>(z, Z_DIM, W_zi, Z_DIM, b_zi, p_zin, BS, Z_IN, Z_DIM);
    // gi = z_in @ W_ih[:,3:]^T + b_ih
    gemm_tf32<<<dim3(G3 / BN, BS / BM), 256>>>(p_zin, Z_IN, W_ih + OUT_DIM, X_DIM, b_ih, p_gi, BS, G3, Z_IN);
    // h0 tf32 copy into ping buffer
    conv_h_kernel<<<(BS * HID + 255) / 256, 256>>>();

    for (int t = 0; t < N_STEP; t++) {
        const float* hsrc = (t & 1) ? p_hb : p_ha;
        float*       hdst = (t & 1) ? p_ha : p_hb;
        fused_step<<<dim3(HID / FBU, BS / FBM), 256, FUSED_SMEM_BYTES>>>(hsrc, hdst, b_hh);
        out_head<<<BS, 128>>>(W_out, b_out, recon, t);
    }
}

// round 5
// speedup vs baseline: 2.5185x; 1.0023x over previous
#include <cuda_runtime.h>
#include <cuda_bf16.h>
#include <cstdint>

// Problem constants
#define BS      4096
#define Z_DIM   512
#define HID     1024
#define Z_IN    128
#define N_STEP  32
#define OUT_DIM 3
#define G3      (3*HID)        // 3072
#define X_DIM   (OUT_DIM+Z_IN) // 131

// Scratch (device globals — no allocation allowed)
__device__ float g_h[BS * HID];        // exact hidden state
__device__ float g_htf_a[BS * HID];    // tf32-rounded hidden, ping
__device__ float g_htf_b[BS * HID];    // tf32-rounded hidden, pong
__device__ float g_gi[BS * G3];        // z_in part of input gates (+b_ih)
__device__ float g_zin[BS * Z_IN];
__device__ float g_token[BS * OUT_DIM];
__device__ float g_tokw[G3 * OUT_DIM]; // W_ih[:, 0:3] compacted
__device__ float g_Wt[G3 * HID];       // tf32-rounded W_hh

// ---------------------------------------------------------------------------
// helpers
// ---------------------------------------------------------------------------
__device__ __forceinline__ float to_tf32(float x) {
    uint32_t r;
    asm("cvt.rna.tf32.f32 %0, %1;" : "=r"(r) : "f"(x));
    return __uint_as_float(r);
}

__device__ __forceinline__ void mma_m16n8k8_tf32(float* c, const uint32_t* a, const uint32_t* b) {
    asm volatile(
        "mma.sync.aligned.m16n8k8.row.col.f32.tf32.tf32.f32 "
        "{%0,%1,%2,%3}, {%4,%5,%6,%7}, {%8,%9}, {%0,%1,%2,%3};\n"
        : "+f"(c[0]), "+f"(c[1]), "+f"(c[2]), "+f"(c[3])
        : "r"(a[0]), "r"(a[1]), "r"(a[2]), "r"(a[3]),
          "r"(b[0]), "r"(b[1]));
}

// EXACT activations (match round-1/4 passing numerics)
__device__ __forceinline__ float sigmoidf(float x) {
    return 1.0f / (1.0f + expf(-x));
}

__device__ __forceinline__ void cp16(uint32_t dst, const float* src) {
    asm volatile("cp.async.cg.shared.global [%0], [%1], 16;" :: "r"(dst), "l"(src));
}
#define CP_COMMIT() asm volatile("cp.async.commit_group;")
#define CP_WAIT(n)  asm volatile("cp.async.wait_group %0;" :: "n"(n))

// ---------------------------------------------------------------------------
// Prologue GEMM: C[M,N] = A[M,K](lda) * B[N,K](ldb)^T + bias[N]
// ---------------------------------------------------------------------------
#define BM 128
#define BN 128
#define BK 32

__global__ void __launch_bounds__(256)
gemm_tf32(const float* __restrict__ A, int lda,
          const float* __restrict__ B, int ldb,
          const float* __restrict__ bias,
          float* __restrict__ C,
          int M, int N, int K)
{
    __shared__ float As[BM][BK + 4];
    __shared__ float Bs[BN][BK + 4];

    const int m0   = blockIdx.y * BM;
    const int n0   = blockIdx.x * BN;
    const int tid  = threadIdx.x;
    const int lane = tid & 31;
    const int warp = tid >> 5;
    const int wm   = warp & 3;
    const int wn   = warp >> 2;
    const int gid  = lane >> 2;
    const int l4   = lane & 3;

    float acc[2][8][4];
#pragma unroll
    for (int mt = 0; mt < 2; mt++)
#pragma unroll
        for (int nt = 0; nt < 8; nt++)
#pragma unroll
            for (int i = 0; i < 4; i++) acc[mt][nt][i] = 0.0f;

    for (int kt = 0; kt < K; kt += BK) {
#pragma unroll
        for (int i = 0; i < 16; i++) {
            int e = tid + i * 256;
            int r = e >> 5, c = e & 31;
            As[r][c] = to_tf32(A[(size_t)(m0 + r) * lda + kt + c]);
        }
#pragma unroll
        for (int i = 0; i < 16; i++) {
            int e = tid + i * 256;
            int r = e >> 5, c = e & 31;
            Bs[r][c] = to_tf32(B[(size_t)(n0 + r) * ldb + kt + c]);
        }
        __syncthreads();

#pragma unroll
        for (int kk = 0; kk < BK; kk += 8) {
            uint32_t af[2][4], bf[8][2];
#pragma unroll
            for (int mt = 0; mt < 2; mt++) {
                int rb = wm * 32 + mt * 16 + gid;
                af[mt][0] = __float_as_uint(As[rb    ][kk + l4    ]);
                af[mt][1] = __float_as_uint(As[rb + 8][kk + l4    ]);
                af[mt][2] = __float_as_uint(As[rb    ][kk + l4 + 4]);
                af[mt][3] = __float_as_uint(As[rb + 8][kk + l4 + 4]);
            }
#pragma unroll
            for (int nt = 0; nt < 8; nt++) {
                int rb = wn * 64 + nt * 8 + gid;
                bf[nt][0] = __float_as_uint(Bs[rb][kk + l4    ]);
                bf[nt][1] = __float_as_uint(Bs[rb][kk + l4 + 4]);
            }
#pragma unroll
            for (int mt = 0; mt < 2; mt++)
#pragma unroll
                for (int nt = 0; nt < 8; nt++)
                    mma_m16n8k8_tf32(acc[mt][nt], af[mt], bf[nt]);
        }
        __syncthreads();
    }

#pragma unroll
    for (int mt = 0; mt < 2; mt++) {
#pragma unroll
        for (int nt = 0; nt < 8; nt++) {
            int row = m0 + wm * 32 + mt * 16 + gid;
            int col = n0 + wn * 64 + nt * 8 + l4 * 2;
            float b0 = bias[col], b1 = bias[col + 1];
            float* p0 = &C[(size_t)row * N + col];
            float* p1 = &C[(size_t)(row + 8) * N + col];
            p0[0] = acc[mt][nt][0] + b0;
            p0[1] = acc[mt][nt][1] + b1;
            p1[0] = acc[mt][nt][2] + b0;
            p1[1] = acc[mt][nt][3] + b1;
        }
    }
}

// ---------------------------------------------------------------------------
// Setup + converts
// ---------------------------------------------------------------------------
__global__ void setup_kernel(const float* __restrict__ W_ih,
                             const float* __restrict__ init_input)
{
    int i = blockIdx.x * blockDim.x + threadIdx.x;
    if (i < G3 * OUT_DIM)
        g_tokw[i] = W_ih[(i / OUT_DIM) * X_DIM + (i % OUT_DIM)];
    if (i < BS * OUT_DIM)
        g_token[i] = init_input[i % OUT_DIM];
}

__global__ void conv_w_kernel(const float* __restrict__ W_hh) {
    int i = blockIdx.x * blockDim.x + threadIdx.x;
    if (i < G3 * HID) g_Wt[i] = to_tf32(W_hh[i]);
}
__global__ void conv_h_kernel() {
    int i = blockIdx.x * blockDim.x + threadIdx.x;
    if (i < BS * HID) g_htf_a[i] = to_tf32(g_h[i]);
}

// ---------------------------------------------------------------------------
// Fused step kernel: gh = h @ W_hh^T (3 gates) fused with GRU update.
// CTA tile: 128 rows x 64 units x 3 gates. 256 threads.
// 3-stage cp.async pipeline, ONE __syncthreads per k-tile, register-level
// fragment double buffering for LDS->MMA latency hiding.
// ---------------------------------------------------------------------------
#define FBM 128
#define FBU 64
#define FBN 192
#define FBK 32
#define FST 36                      // row stride in floats (BK + 4 pad)
#define NSTAGE 3
#define A_STG_F (FBM*FST)           // 4608 floats per stage
#define B_STG_F (FBN*FST)           // 6912 floats per stage
#define SB_OFF_F (NSTAGE*A_STG_F)   // 13824
#define EXTRA_OFF_F (SB_OFF_F + NSTAGE*B_STG_F)   // 34560
#define FUSED_SMEM_BYTES ((EXTRA_OFF_F + FBM*3 + FBN*3 + FBN) * 4)  // 142848

__global__ void __launch_bounds__(256)
fused_step(const float* __restrict__ hsrc,   // tf32 h(t), read-only
           float* __restrict__ hdst,         // tf32 h(t+1), write-only
           const float* __restrict__ b_hh)
{
    extern __shared__ float smem[];
    float* s_tok = smem + EXTRA_OFF_F;          // [FBM*3]
    float* s_tw  = s_tok + FBM * 3;             // [(g*64+u)*3 + j]
    float* s_bh  = s_tw + FBN * 3;              // [g*64+u]

    const int n0  = blockIdx.x * FBU;
    const int m0  = blockIdx.y * FBM;
    const int tid = threadIdx.x;
    const int lane = tid & 31;
    const int warp = tid >> 5;
    const int wm = warp & 3;        // 4 warps along M (32 rows each)
    const int wn = warp >> 2;       // 2 warps along N (32 units each)
    const int gid = lane >> 2;
    const int l4  = lane & 3;

    // stage constant epilogue data
    for (int e = tid; e < FBM * 3; e += 256) s_tok[e] = g_token[m0 * 3 + e];
    for (int e = tid; e < FBN * 3; e += 256) {
        int rg = e / 3, j = e - rg * 3;
        int g = rg >> 6, u = rg & 63;
        s_tw[e] = g_tokw[((size_t)g * HID + n0 + u) * 3 + j];
    }
    if (tid < FBN) s_bh[tid] = b_hh[(tid >> 6) * HID + n0 + (tid & 63)];

    // per-thread cp.async coordinates
    uint32_t sbase = (uint32_t)__cvta_generic_to_shared(smem);
    uint32_t aoffs[4]; const float* agp[4];
#pragma unroll
    for (int i = 0; i < 4; i++) {
        int c = tid + i * 256;
        int r = c >> 3, j = c & 7;
        aoffs[i] = sbase + (uint32_t)(r * FST + j * 4) * 4u;
        agp[i]   = hsrc + (size_t)(m0 + r) * HID + j * 4;
    }
    uint32_t boffs[6]; const float* bgp[6];
#pragma unroll
    for (int i = 0; i < 6; i++) {
        int c = tid + i * 256;
        int r = c >> 3, j = c & 7;
        boffs[i] = sbase + (uint32_t)(SB_OFF_F + r * FST + j * 4) * 4u;
        bgp[i]   = g_Wt + (size_t)((r >> 6) * HID + n0 + (r & 63)) * HID + j * 4;
    }

    float acc[3][2][4][4];
#pragma unroll
    for (int g = 0; g < 3; g++)
#pragma unroll
        for (int mt = 0; mt < 2; mt++)
#pragma unroll
            for (int nt = 0; nt < 4; nt++)
#pragma unroll
                for (int i = 0; i < 4; i++) acc[g][mt][nt][i] = 0.0f;

    auto issue = [&](int st, int kt) {
#pragma unroll
        for (int i = 0; i < 4; i++) cp16(aoffs[i] + (uint32_t)st * (A_STG_F * 4), agp[i] + kt);
#pragma unroll
        for (int i = 0; i < 6; i++) cp16(boffs[i] + (uint32_t)st * (B_STG_F * 4), bgp[i] + kt);
    };

    const int NKT = HID / FBK;   // 32

    // prologue: fill stages 0 and 1
    issue(0, 0);        CP_COMMIT();
    issue(1, FBK);      CP_COMMIT();

    // frag register double-buffers
    uint32_t af[2][2][4];
    uint32_t bf[2][12][2];

    // fragment loaders (chunk kk within the staged tile)
    auto ldA = [&](uint32_t a[2][4], const float* Af, int kk) {
#pragma unroll
        for (int mt = 0; mt < 2; mt++) {
            int rb = wm * 32 + mt * 16 + gid;
            a[mt][0] = __float_as_uint(Af[rb * FST + kk + l4]);
            a[mt][1] = __float_as_uint(Af[(rb + 8) * FST + kk + l4]);
            a[mt][2] = __float_as_uint(Af[rb * FST + kk + l4 + 4]);
            a[mt][3] = __float_as_uint(Af[(rb + 8) * FST + kk + l4 + 4]);
        }
    };
    auto ldB = [&](uint32_t b[12][2], const float* Bf, int kk) {
#pragma unroll
        for (int g = 0; g < 3; g++)
#pragma unroll
            for (int nt = 0; nt < 4; nt++) {
                int rb = g * 64 + wn * 32 + nt * 8 + gid;
                b[g * 4 + nt][0] = __float_as_uint(Bf[rb * FST + kk + l4]);
                b[g * 4 + nt][1] = __float_as_uint(Bf[rb * FST + kk + l4 + 4]);
            }
    };

    for (int it = 0; it < NKT; ++it) {
        CP_WAIT(1);                 // stage it%3 is ready
        __syncthreads();            // all warps done reading stage (it+2)%3 (from it-1)

        // prefetch stage it+2 into slot (it+2)%3 (overlaps the MMA phase below)
        if (it + 2 < NKT) issue((it + 2) % NSTAGE, (it + 2) * FBK);
        CP_COMMIT();                // empty group near the tail keeps the wait count uniform

        const float* Af = smem + (it % NSTAGE) * A_STG_F;
        const float* Bf = smem + SB_OFF_F + (it % NSTAGE) * B_STG_F;

        ldA(af[0], Af, 0);
        ldB(bf[0], Bf, 0);

#pragma unroll
        for (int c = 0; c < 4; c++) {
            int cur = c & 1, nxt = cur ^ 1;
            if (c < 3) {            // prefetch next chunk's fragments
                ldA(af[nxt], Af, (c + 1) * 8);
                ldB(bf[nxt], Bf, (c + 1) * 8);
            }
#pragma unroll
            for (int g = 0; g < 3; g++)
#pragma unroll
                for (int nt = 0; nt < 4; nt++) {
                    mma_m16n8k8_tf32(acc[g][0][nt], af[cur][0], bf[cur][g * 4 + nt]);
                    mma_m16n8k8_tf32(acc[g][1][nt], af[cur][1], bf[cur][g * 4 + nt]);
                }
        }
    }

    // ---- epilogue: GRU update in-register (exact activations) ----
#pragma unroll
    for (int mt = 0; mt < 2; mt++) {
#pragma unroll
        for (int rs = 0; rs < 2; rs++) {
            int rloc = wm * 32 + mt * 16 + gid + rs * 8;
            int grow = m0 + rloc;
            float t0 = s_tok[rloc * 3 + 0];
            float t1 = s_tok[rloc * 3 + 1];
            float t2 = s_tok[rloc * 3 + 2];
            const float* gi = g_gi + (size_t)grow * G3;
            float* hrow  = g_h  + (size_t)grow * HID;
            float* hfrow = hdst + (size_t)grow * HID;
#pragma unroll
            for (int nt = 0; nt < 4; nt++) {
                int ul = wn * 32 + nt * 8 + l4 * 2;   // local unit (even)
                int gu = n0 + ul;
                float2 gr  = *(const float2*)(gi + gu);
                float2 gu2 = *(const float2*)(gi + HID + gu);
                float2 gn  = *(const float2*)(gi + 2 * HID + gu);
                float2 h2  = *(const float2*)(hrow + gu);

                float hn_out[2];
#pragma unroll
                for (int c = 0; c < 2; c++) {
                    int u = ul + c;
                    float acc_r = acc[0][mt][nt][rs * 2 + c];
                    float acc_u = acc[1][mt][nt][rs * 2 + c];
                    float acc_n = acc[2][mt][nt][rs * 2 + c];
                    float gi_r = (c ? gr.y  : gr.x);
                    float gi_u = (c ? gu2.y : gu2.x);
                    float gi_n = (c ? gn.y  : gn.x);
                    float hold = (c ? h2.y  : h2.x);

                    float ir = gi_r + t0 * s_tw[(0 * 64 + u) * 3 + 0]
                                    + t1 * s_tw[(0 * 64 + u) * 3 + 1]
                                    + t2 * s_tw[(0 * 64 + u) * 3 + 2];
                    float iu = gi_u + t0 * s_tw[(1 * 64 + u) * 3 + 0]
                                    + t1 * s_tw[(1 * 64 + u) * 3 + 1]
                                    + t2 * s_tw[(1 * 64 + u) * 3 + 2];
                    float in_ = gi_n + t0 * s_tw[(2 * 64 + u) * 3 + 0]
                                     + t1 * s_tw[(2 * 64 + u) * 3 + 1]
                                     + t2 * s_tw[(2 * 64 + u) * 3 + 2];

                    float hr = acc_r + s_bh[u];
                    float hu = acc_u + s_bh[64 + u];
                    float hn = acc_n + s_bh[128 + u];

                    float r  = sigmoidf(ir + hr);
                    float uu = sigmoidf(iu + hu);
                    float n  = tanhf(in_ + r * hn);
                    hn_out[c] = (1.0f - uu) * n + uu * hold;
                }
                *(float2*)(hrow + gu)  = make_float2(hn_out[0], hn_out[1]);
                *(float2*)(hfrow + gu) = make_float2(to_tf32(hn_out[0]), to_tf32(hn_out[1]));
            }
        }
    }
}

// ---------------------------------------------------------------------------
// Output head: o = h_new @ W_out^T + b_out; recon + next token. 1 block/row.
// float4-vectorized.
// ---------------------------------------------------------------------------
__global__ void __launch_bounds__(128)
out_head(const float* __restrict__ W_out,
         const float* __restrict__ b_out,
         float* __restrict__ recon,
         int t)
{
    const int row = blockIdx.x;
    const int tid = threadIdx.x;
    const int lane = tid & 31;
    const int warp = tid >> 5;
    __shared__ float red[3][4];

    const float4* h4 = (const float4*)(g_h + (size_t)row * HID);
    const float4* w0 = (const float4*)(W_out);
    const float4* w1 = (const float4*)(W_out + HID);
    const float4* w2 = (const float4*)(W_out + 2 * HID);

    float s0 = 0.f, s1 = 0.f, s2 = 0.f;
#pragma unroll
    for (int i = 0; i < HID / (128 * 4); i++) {
        int idx = tid + i * 128;
        float4 hv = h4[idx];
        float4 a = w0[idx], b = w1[idx], c = w2[idx];
        s0 += hv.x * a.x + hv.y * a.y + hv.z * a.z + hv.w * a.w;
        s1 += hv.x * b.x + hv.y * b.y + hv.z * b.z + hv.w * b.w;
        s2 += hv.x * c.x + hv.y * c.y + hv.z * c.z + hv.w * c.w;
    }
#pragma unroll
    for (int off = 16; off > 0; off >>= 1) {
        s0 += __shfl_down_sync(0xffffffffu, s0, off);
        s1 += __shfl_down_sync(0xffffffffu, s1, off);
        s2 += __shfl_down_sync(0xffffffffu, s2, off);
    }
    if (lane == 0) { red[0][warp] = s0; red[1][warp] = s1; red[2][warp] = s2; }
    __syncthreads();
    if (tid == 0) {
        float a0 = red[0][0] + red[0][1] + red[0][2] + red[0][3];
        float a1 = red[1][0] + red[1][1] + red[1][2] + red[1][3];
        float a2 = red[2][0] + red[2][1] + red[2][2] + red[2][3];
        float bass    = sigmoidf(a0 + b_out[0]);
        float rhy_int = a1 + b_out[1];
        float rhy     = sigmoidf(a2 + b_out[2]);

        float* rc = recon + (size_t)row * (N_STEP * OUT_DIM) + t * OUT_DIM;
        rc[0] = bass; rc[1] = rhy_int; rc[2] = rhy;

        g_token[row * 3 + 0] = bass;
        g_token[row * 3 + 1] = rhy_int;
        g_token[row * 3 + 2] = (rhy > 0.5f) ? 1.0f : 0.0f;
    }
}

// ---------------------------------------------------------------------------
// kernel_launch
// inputs: 0 z, 1 inference, 2 tfr, 3 W_zh, 4 b_zh, 5 W_zi, 6 b_zi,
//         7 W_ih, 8 b_ih, 9 W_hh, 10 b_hh, 11 W_out, 12 b_out, 13 init_input
// ---------------------------------------------------------------------------
extern "C" void kernel_launch(void* const* d_in, const int* in_sizes, int n_in,
                              void* d_out, int out_size)
{
    (void)in_sizes; (void)n_in; (void)out_size;

    const float* z      = (const float*)d_in[0];
    const float* W_zh   = (const float*)d_in[3];
    const float* b_zh   = (const float*)d_in[4];
    const float* W_zi   = (const float*)d_in[5];
    const float* b_zi   = (const float*)d_in[6];
    const float* W_ih   = (const float*)d_in[7];
    const float* b_ih   = (const float*)d_in[8];
    const float* W_hh   = (const float*)d_in[9];
    const float* b_hh   = (const float*)d_in[10];
    const float* W_out  = (const float*)d_in[11];
    const float* b_out  = (const float*)d_in[12];
    const float* initin = (const float*)d_in[13];
    float* recon = (float*)d_out;

    float *p_h, *p_gi, *p_zin, *p_ha, *p_hb;
    cudaGetSymbolAddress((void**)&p_h,   g_h);
    cudaGetSymbolAddress((void**)&p_gi,  g_gi);
    cudaGetSymbolAddress((void**)&p_zin, g_zin);
    cudaGetSymbolAddress((void**)&p_ha,  g_htf_a);
    cudaGetSymbolAddress((void**)&p_hb,  g_htf_b);

    cudaFuncSetAttribute(fused_step, cudaFuncAttributeMaxDynamicSharedMemorySize,
                         FUSED_SMEM_BYTES);

    // setup + weight conversion
    setup_kernel<<<48, 256>>>(W_ih, initin);
    conv_w_kernel<<<(G3 * HID + 255) / 256, 256>>>(W_hh);

    // h0 = z @ W_zh^T + b_zh
    gemm_tf32<<<dim3(HID / BN, BS / BM), 256>>>(z, Z_DIM, W_zh, Z_DIM, b_zh, p_h, BS, HID, Z_DIM);
    // z_in = z @ W_zi^T + b_zi
    gemm_tf32<<<dim3(Z_IN / BN, BS / BM), 256>>>(z, Z_DIM, W_zi, Z_DIM, b_zi, p_zin, BS, Z_IN, Z_DIM);
    // gi = z_in @ W_ih[:,3:]^T + b_ih
    gemm_tf32<<<dim3(G3 / BN, BS / BM), 256>>>(p_zin, Z_IN, W_ih + OUT_DIM, X_DIM, b_ih, p_gi, BS, G3, Z_IN);
    // h0 tf32 copy into ping buffer
    conv_h_kernel<<<(BS * HID + 255) / 256, 256>>>();

    for (int t = 0; t < N_STEP; t++) {
        const float* hsrc = (t & 1) ? p_hb : p_ha;
        float*       hdst = (t & 1) ? p_ha : p_hb;
        fused_step<<<dim3(HID / FBU, BS / FBM), 256, FUSED_SMEM_BYTES>>>(hsrc, hdst, b_hh);
        out_head<<<BS, 128>>>(W_out, b_out, recon, t);
    }
}

// round 7
// speedup vs baseline: 3.7641x; 1.4946x over previous
#include <cuda_runtime.h>
#include <cuda_fp16.h>
#include <cstdint>

// Problem constants
#define BS      4096
#define Z_DIM   512
#define HID     1024
#define Z_IN    128
#define N_STEP  32
#define OUT_DIM 3
#define G3      (3*HID)        // 3072
#define X_DIM   (OUT_DIM+Z_IN) // 131

// Scratch (device globals — no allocation allowed)
__device__ float  g_h[BS * HID];       // exact hidden state (fp32)
__device__ __half g_hh_a[BS * HID];    // fp16 hidden, ping (GEMM A operand)
__device__ __half g_hh_b[BS * HID];    // fp16 hidden, pong
__device__ float  g_gi[BS * G3];       // z_in part of input gates (+b_ih)
__device__ float  g_zin[BS * Z_IN];
__device__ float  g_token[BS * OUT_DIM];
__device__ float  g_tokw[G3 * OUT_DIM];// W_ih[:, 0:3] compacted
__device__ __half g_Wh[G3 * HID];      // fp16 W_hh

// ---------------------------------------------------------------------------
// helpers
// ---------------------------------------------------------------------------
__device__ __forceinline__ float to_tf32(float x) {
    uint32_t r;
    asm("cvt.rna.tf32.f32 %0, %1;" : "=r"(r) : "f"(x));
    return __uint_as_float(r);
}

__device__ __forceinline__ void mma_m16n8k8_tf32(float* c, const uint32_t* a, const uint32_t* b) {
    asm volatile(
        "mma.sync.aligned.m16n8k8.row.col.f32.tf32.tf32.f32 "
        "{%0,%1,%2,%3}, {%4,%5,%6,%7}, {%8,%9}, {%0,%1,%2,%3};\n"
        : "+f"(c[0]), "+f"(c[1]), "+f"(c[2]), "+f"(c[3])
        : "r"(a[0]), "r"(a[1]), "r"(a[2]), "r"(a[3]),
          "r"(b[0]), "r"(b[1]));
}

// fp16 MMA: m16n8k16, fp32 accumulate
__device__ __forceinline__ void mma_m16n8k16_f16(float* c, const uint32_t* a, const uint32_t* b) {
    asm volatile(
        "mma.sync.aligned.m16n8k16.row.col.f32.f16.f16.f32 "
        "{%0,%1,%2,%3}, {%4,%5,%6,%7}, {%8,%9}, {%0,%1,%2,%3};\n"
        : "+f"(c[0]), "+f"(c[1]), "+f"(c[2]), "+f"(c[3])
        : "r"(a[0]), "r"(a[1]), "r"(a[2]), "r"(a[3]),
          "r"(b[0]), "r"(b[1]));
}

// EXACT activations (passing-round numerics)
__device__ __forceinline__ float sigmoidf(float x) {
    return 1.0f / (1.0f + expf(-x));
}

__device__ __forceinline__ void cp16(uint32_t dst, const void* src) {
    asm volatile("cp.async.cg.shared.global [%0], [%1], 16;" :: "r"(dst), "l"(src));
}
#define CP_COMMIT() asm volatile("cp.async.commit_group;")
#define CP_WAIT(n)  asm volatile("cp.async.wait_group %0;" :: "n"(n))

// ---------------------------------------------------------------------------
// Prologue GEMM (tf32, off critical path):
// C[M,N] = A[M,K](lda) * B[N,K](ldb)^T + bias[N]; optional fp16 dup output.
// ---------------------------------------------------------------------------
#define BM 128
#define BN 128
#define BK 32

__global__ void __launch_bounds__(256)
gemm_tf32(const float* __restrict__ A, int lda,
          const float* __restrict__ B, int ldb,
          const float* __restrict__ bias,
          float* __restrict__ C,
          __half* __restrict__ Cdup,    // optional fp16 copy (may be null)
          int M, int N, int K)
{
    __shared__ float As[BM][BK + 4];
    __shared__ float Bs[BN][BK + 4];

    const int m0   = blockIdx.y * BM;
    const int n0   = blockIdx.x * BN;
    const int tid  = threadIdx.x;
    const int lane = tid & 31;
    const int warp = tid >> 5;
    const int wm   = warp & 3;
    const int wn   = warp >> 2;
    const int gid  = lane >> 2;
    const int l4   = lane & 3;

    float acc[2][8][4];
#pragma unroll
    for (int mt = 0; mt < 2; mt++)
#pragma unroll
        for (int nt = 0; nt < 8; nt++)
#pragma unroll
            for (int i = 0; i < 4; i++) acc[mt][nt][i] = 0.0f;

    for (int kt = 0; kt < K; kt += BK) {
#pragma unroll
        for (int i = 0; i < 16; i++) {
            int e = tid + i * 256;
            int r = e >> 5, c = e & 31;
            As[r][c] = to_tf32(A[(size_t)(m0 + r) * lda + kt + c]);
        }
#pragma unroll
        for (int i = 0; i < 16; i++) {
            int e = tid + i * 256;
            int r = e >> 5, c = e & 31;
            Bs[r][c] = to_tf32(B[(size_t)(n0 + r) * ldb + kt + c]);
        }
        __syncthreads();

#pragma unroll
        for (int kk = 0; kk < BK; kk += 8) {
            uint32_t af[2][4], bf[8][2];
#pragma unroll
            for (int mt = 0; mt < 2; mt++) {
                int rb = wm * 32 + mt * 16 + gid;
                af[mt][0] = __float_as_uint(As[rb    ][kk + l4    ]);
                af[mt][1] = __float_as_uint(As[rb + 8][kk + l4    ]);
                af[mt][2] = __float_as_uint(As[rb    ][kk + l4 + 4]);
                af[mt][3] = __float_as_uint(As[rb + 8][kk + l4 + 4]);
            }
#pragma unroll
            for (int nt = 0; nt < 8; nt++) {
                int rb = wn * 64 + nt * 8 + gid;
                bf[nt][0] = __float_as_uint(Bs[rb][kk + l4    ]);
                bf[nt][1] = __float_as_uint(Bs[rb][kk + l4 + 4]);
            }
#pragma unroll
            for (int mt = 0; mt < 2; mt++)
#pragma unroll
                for (int nt = 0; nt < 8; nt++)
                    mma_m16n8k8_tf32(acc[mt][nt], af[mt], bf[nt]);
        }
        __syncthreads();
    }

#pragma unroll
    for (int mt = 0; mt < 2; mt++) {
#pragma unroll
        for (int nt = 0; nt < 8; nt++) {
            int row = m0 + wm * 32 + mt * 16 + gid;
            int col = n0 + wn * 64 + nt * 8 + l4 * 2;
            float b0 = bias[col], b1 = bias[col + 1];
            float v00 = acc[mt][nt][0] + b0;
            float v01 = acc[mt][nt][1] + b1;
            float v10 = acc[mt][nt][2] + b0;
            float v11 = acc[mt][nt][3] + b1;
            float* p0 = &C[(size_t)row * N + col];
            float* p1 = &C[(size_t)(row + 8) * N + col];
            p0[0] = v00; p0[1] = v01;
            p1[0] = v10; p1[1] = v11;
            if (Cdup) {
                *(half2*)&Cdup[(size_t)row * N + col]       = __floats2half2_rn(v00, v01);
                *(half2*)&Cdup[(size_t)(row + 8) * N + col] = __floats2half2_rn(v10, v11);
            }
        }
    }
}

// ---------------------------------------------------------------------------
// Setup: token init, token-weight compaction, W_hh fp16 conversion
// ---------------------------------------------------------------------------
__global__ void setup_kernel(const float* __restrict__ W_ih,
                             const float* __restrict__ W_hh,
                             const float* __restrict__ init_input)
{
    int i = blockIdx.x * blockDim.x + threadIdx.x;
    if (i < G3 * OUT_DIM)
        g_tokw[i] = W_ih[(i / OUT_DIM) * X_DIM + (i % OUT_DIM)];
    if (i < BS * OUT_DIM)
        g_token[i] = init_input[i % OUT_DIM];
    for (int j = i; j < G3 * HID; j += gridDim.x * blockDim.x)
        g_Wh[j] = __float2half(W_hh[j]);
}

// ---------------------------------------------------------------------------
// Fused step kernel: gh = h @ W_hh^T (3 gates) fused with GRU update.
// fp16 operands (m16n8k16), fp32 accumulate. CTA: 128 rows x 64 units x 3 gates.
// 256 threads. 3-stage cp.async pipeline (round-5 skeleton), smem in half.
// ---------------------------------------------------------------------------
#define FBM 128
#define FBU 64
#define FBN 192
#define FBK 32                     // k-elements per staged tile
#define FSTH 40                    // row stride in halves (32 + 8 pad; 80B, 16B-aligned)
#define NSTAGE 3
#define A_STG_B (FBM*FSTH*2)       // 10240 bytes per stage
#define B_STG_B (FBN*FSTH*2)       // 15360 bytes per stage
#define SB_OFF_B (NSTAGE*A_STG_B)                 // 30720
#define EXTRA_OFF_B (SB_OFF_B + NSTAGE*B_STG_B)   // 76800
#define FUSED_SMEM_BYTES (EXTRA_OFF_B + (FBM*3 + FBN*3 + FBN) * 4)  // 81408

__global__ void __launch_bounds__(256)
fused_step(const __half* __restrict__ hsrc,  // fp16 h(t), read-only
           __half* __restrict__ hdst,        // fp16 h(t+1), write-only
           const float* __restrict__ b_hh)
{
    extern __shared__ char smemc[];
    float* s_tok = (float*)(smemc + EXTRA_OFF_B);           // [FBM*3]
    float* s_tw  = s_tok + FBM * 3;                         // [(g*64+u)*3 + j]
    float* s_bh  = s_tw + FBN * 3;                          // [g*64+u]

    const int n0  = blockIdx.x * FBU;
    const int m0  = blockIdx.y * FBM;
    const int tid = threadIdx.x;
    const int lane = tid & 31;
    const int warp = tid >> 5;
    const int wm = warp & 3;        // 4 warps along M (32 rows each)
    const int wn = warp >> 2;       // 2 warps along N (32 units each)
    const int gid = lane >> 2;
    const int l4  = lane & 3;

    // stage constant epilogue data
    for (int e = tid; e < FBM * 3; e += 256) s_tok[e] = g_token[m0 * 3 + e];
    for (int e = tid; e < FBN * 3; e += 256) {
        int rg = e / 3, j = e - rg * 3;
        int g = rg >> 6, u = rg & 63;
        s_tw[e] = g_tokw[((size_t)g * HID + n0 + u) * 3 + j];
    }
    if (tid < FBN) s_bh[tid] = b_hh[(tid >> 6) * HID + n0 + (tid & 63)];

    // per-thread cp.async coordinates (16B = 8 halves per op)
    uint32_t sbase = (uint32_t)__cvta_generic_to_shared(smemc);
    uint32_t adst[2]; const __half* asrc[2];
#pragma unroll
    for (int i = 0; i < 2; i++) {
        int e = tid + i * 256;          // 512 chunks: 128 rows x 4
        int r = e >> 2, j = e & 3;
        adst[i] = sbase + (uint32_t)(r * (FSTH * 2) + j * 16);
        asrc[i] = hsrc + (size_t)(m0 + r) * HID + j * 8;
    }
    uint32_t bdst[3]; const __half* bsrc[3];
#pragma unroll
    for (int i = 0; i < 3; i++) {
        int e = tid + i * 256;          // 768 chunks: 192 rows x 4
        int r = e >> 2, j = e & 3;
        bdst[i] = sbase + (uint32_t)(SB_OFF_B + r * (FSTH * 2) + j * 16);
        bsrc[i] = g_Wh + (size_t)((r >> 6) * HID + n0 + (r & 63)) * HID + j * 8;
    }

    float acc[3][2][4][4];
#pragma unroll
    for (int g = 0; g < 3; g++)
#pragma unroll
        for (int mt = 0; mt < 2; mt++)
#pragma unroll
            for (int nt = 0; nt < 4; nt++)
#pragma unroll
                for (int i = 0; i < 4; i++) acc[g][mt][nt][i] = 0.0f;

    auto issue = [&](int st, int kt) {
#pragma unroll
        for (int i = 0; i < 2; i++) cp16(adst[i] + (uint32_t)st * A_STG_B, asrc[i] + kt);
#pragma unroll
        for (int i = 0; i < 3; i++) cp16(bdst[i] + (uint32_t)st * B_STG_B, bsrc[i] + kt);
    };

    const int NKT = HID / FBK;   // 32

    // prologue: fill stages 0 and 1
    issue(0, 0);        CP_COMMIT();
    issue(1, FBK);      CP_COMMIT();

    for (int it = 0; it < NKT; ++it) {
        CP_WAIT(1);                 // stage it%3 is ready
        __syncthreads();            // all warps done reading stage (it+2)%3 (iter it-1)

        if (it + 2 < NKT) issue((it + 2) % NSTAGE, (it + 2) * FBK);
        CP_COMMIT();

        // word-level views of the staged tiles (2 halves per 32-bit word)
        const uint32_t* Aw = (const uint32_t*)(smemc + (it % NSTAGE) * A_STG_B);
        const uint32_t* Bw = (const uint32_t*)(smemc + SB_OFF_B + (it % NSTAGE) * B_STG_B);

#pragma unroll
        for (int ks = 0; ks < 2; ks++) {        // two k16 steps per 32-wide tile
            const int kw = ks * 8 + l4;         // word offset within row (FSTH/2=20 words)
            uint32_t a[2][4];
#pragma unroll
            for (int mt = 0; mt < 2; mt++) {
                int rb = wm * 32 + mt * 16 + gid;
                a[mt][0] = Aw[rb * 20 + kw];
                a[mt][1] = Aw[(rb + 8) * 20 + kw];
                a[mt][2] = Aw[rb * 20 + kw + 4];
                a[mt][3] = Aw[(rb + 8) * 20 + kw + 4];
            }
#pragma unroll
            for (int g = 0; g < 3; g++)
#pragma unroll
                for (int nt = 0; nt < 4; nt++) {
                    int rb = g * 64 + wn * 32 + nt * 8 + gid;
                    uint32_t b[2];
                    b[0] = Bw[rb * 20 + kw];
                    b[1] = Bw[rb * 20 + kw + 4];
                    mma_m16n8k16_f16(acc[g][0][nt], a[0], b);
                    mma_m16n8k16_f16(acc[g][1][nt], a[1], b);
                }
        }
    }

    // ---- epilogue: GRU update in-register (exact activations) ----
#pragma unroll
    for (int mt = 0; mt < 2; mt++) {
#pragma unroll
        for (int rs = 0; rs < 2; rs++) {
            int rloc = wm * 32 + mt * 16 + gid + rs * 8;
            int grow = m0 + rloc;
            float t0 = s_tok[rloc * 3 + 0];
            float t1 = s_tok[rloc * 3 + 1];
            float t2 = s_tok[rloc * 3 + 2];
            const float* gi = g_gi + (size_t)grow * G3;
            float*  hrow  = g_h  + (size_t)grow * HID;
            __half* hfrow = hdst + (size_t)grow * HID;
#pragma unroll
            for (int nt = 0; nt < 4; nt++) {
                int ul = wn * 32 + nt * 8 + l4 * 2;   // local unit (even)
                int gu = n0 + ul;
                float2 gr  = *(const float2*)(gi + gu);
                float2 gu2 = *(const float2*)(gi + HID + gu);
                float2 gn  = *(const float2*)(gi + 2 * HID + gu);
                float2 h2  = *(const float2*)(hrow + gu);

                float hn_out[2];
#pragma unroll
                for (int c = 0; c < 2; c++) {
                    int u = ul + c;
                    float acc_r = acc[0][mt][nt][rs * 2 + c];
                    float acc_u = acc[1][mt][nt][rs * 2 + c];
                    float acc_n = acc[2][mt][nt][rs * 2 + c];
                    float gi_r = (c ? gr.y  : gr.x);
                    float gi_u = (c ? gu2.y : gu2.x);
                    float gi_n = (c ? gn.y  : gn.x);
                    float hold = (c ? h2.y  : h2.x);

                    float ir = gi_r + t0 * s_tw[(0 * 64 + u) * 3 + 0]
                                    + t1 * s_tw[(0 * 64 + u) * 3 + 1]
                                    + t2 * s_tw[(0 * 64 + u) * 3 + 2];
                    float iu = gi_u + t0 * s_tw[(1 * 64 + u) * 3 + 0]
                                    + t1 * s_tw[(1 * 64 + u) * 3 + 1]
                                    + t2 * s_tw[(1 * 64 + u) * 3 + 2];
                    float in_ = gi_n + t0 * s_tw[(2 * 64 + u) * 3 + 0]
                                     + t1 * s_tw[(2 * 64 + u) * 3 + 1]
                                     + t2 * s_tw[(2 * 64 + u) * 3 + 2];

                    float hr = acc_r + s_bh[u];
                    float hu = acc_u + s_bh[64 + u];
                    float hn = acc_n + s_bh[128 + u];

                    float r  = sigmoidf(ir + hr);
                    float uu = sigmoidf(iu + hu);
                    float n  = tanhf(in_ + r * hn);
                    hn_out[c] = (1.0f - uu) * n + uu * hold;
                }
                *(float2*)(hrow + gu) = make_float2(hn_out[0], hn_out[1]);
                *(half2*)(hfrow + gu) = __floats2half2_rn(hn_out[0], hn_out[1]);
            }
        }
    }
}

// ---------------------------------------------------------------------------
// Output head: o = h_new @ W_out^T + b_out; recon + next token. 1 block/row.
// ---------------------------------------------------------------------------
__global__ void __launch_bounds__(128)
out_head(const float* __restrict__ W_out,
         const float* __restrict__ b_out,
         float* __restrict__ recon,
         int t)
{
    const int row = blockIdx.x;
    const int tid = threadIdx.x;
    const int lane = tid & 31;
    const int warp = tid >> 5;
    __shared__ float red[3][4];

    const float4* h4 = (const float4*)(g_h + (size_t)row * HID);
    const float4* w0 = (const float4*)(W_out);
    const float4* w1 = (const float4*)(W_out + HID);
    const float4* w2 = (const float4*)(W_out + 2 * HID);

    float s0 = 0.f, s1 = 0.f, s2 = 0.f;
#pragma unroll
    for (int i = 0; i < HID / (128 * 4); i++) {
        int idx = tid + i * 128;
        float4 hv = h4[idx];
        float4 a = w0[idx], b = w1[idx], c = w2[idx];
        s0 += hv.x * a.x + hv.y * a.y + hv.z * a.z + hv.w * a.w;
        s1 += hv.x * b.x + hv.y * b.y + hv.z * b.z + hv.w * b.w;
        s2 += hv.x * c.x + hv.y * c.y + hv.z * c.z + hv.w * c.w;
    }
#pragma unroll
    for (int off = 16; off > 0; off >>= 1) {
        s0 += __shfl_down_sync(0xffffffffu, s0, off);
        s1 += __shfl_down_sync(0xffffffffu, s1, off);
        s2 += __shfl_down_sync(0xffffffffu, s2, off);
    }
    if (lane == 0) { red[0][warp] = s0; red[1][warp] = s1; red[2][warp] = s2; }
    __syncthreads();
    if (tid == 0) {
        float a0 = red[0][0] + red[0][1] + red[0][2] + red[0][3];
        float a1 = red[1][0] + red[1][1] + red[1][2] + red[1][3];
        float a2 = red[2][0] + red[2][1] + red[2][2] + red[2][3];
        float bass    = sigmoidf(a0 + b_out[0]);
        float rhy_int = a1 + b_out[1];
        float rhy     = sigmoidf(a2 + b_out[2]);

        float* rc = recon + (size_t)row * (N_STEP * OUT_DIM) + t * OUT_DIM;
        rc[0] = bass; rc[1] = rhy_int; rc[2] = rhy;

        g_token[row * 3 + 0] = bass;
        g_token[row * 3 + 1] = rhy_int;
        g_token[row * 3 + 2] = (rhy > 0.5f) ? 1.0f : 0.0f;
    }
}

// ---------------------------------------------------------------------------
// kernel_launch
// inputs: 0 z, 1 inference, 2 tfr, 3 W_zh, 4 b_zh, 5 W_zi, 6 b_zi,
//         7 W_ih, 8 b_ih, 9 W_hh, 10 b_hh, 11 W_out, 12 b_out, 13 init_input
// ---------------------------------------------------------------------------
extern "C" void kernel_launch(void* const* d_in, const int* in_sizes, int n_in,
                              void* d_out, int out_size)
{
    (void)in_sizes; (void)n_in; (void)out_size;

    const float* z      = (const float*)d_in[0];
    const float* W_zh   = (const float*)d_in[3];
    const float* b_zh   = (const float*)d_in[4];
    const float* W_zi   = (const float*)d_in[5];
    const float* b_zi   = (const float*)d_in[6];
    const float* W_ih   = (const float*)d_in[7];
    const float* b_ih   = (const float*)d_in[8];
    const float* W_hh   = (const float*)d_in[9];
    const float* b_hh   = (const float*)d_in[10];
    const float* W_out  = (const float*)d_in[11];
    const float* b_out  = (const float*)d_in[12];
    const float* initin = (const float*)d_in[13];
    float* recon = (float*)d_out;

    float *p_h, *p_gi, *p_zin;
    __half *p_ha, *p_hb;
    cudaGetSymbolAddress((void**)&p_h,   g_h);
    cudaGetSymbolAddress((void**)&p_gi,  g_gi);
    cudaGetSymbolAddress((void**)&p_zin, g_zin);
    cudaGetSymbolAddress((void**)&p_ha,  g_hh_a);
    cudaGetSymbolAddress((void**)&p_hb,  g_hh_b);

    cudaFuncSetAttribute(fused_step, cudaFuncAttributeMaxDynamicSharedMemorySize,
                         FUSED_SMEM_BYTES);

    // 1: setup (token, tokw, W_hh fp16)
    setup_kernel<<<192, 256>>>(W_ih, W_hh, initin);
    // 2: h0 = z @ W_zh^T + b_zh (+ fp16 dup into ping buffer)
    gemm_tf32<<<dim3(HID / BN, BS / BM), 256>>>(z, Z_DIM, W_zh, Z_DIM, b_zh, p_h, p_ha, BS, HID, Z_DIM);
    // 3: z_in = z @ W_zi^T + b_zi
    gemm_tf32<<<dim3(Z_IN / BN, BS / BM), 256>>>(z, Z_DIM, W_zi, Z_DIM, b_zi, p_zin, nullptr, BS, Z_IN, Z_DIM);
    // 4: gi = z_in @ W_ih[:,3:]^T + b_ih
    gemm_tf32<<<dim3(G3 / BN, BS / BM), 256>>>(p_zin, Z_IN, W_ih + OUT_DIM, X_DIM, b_ih, p_gi, nullptr, BS, G3, Z_IN);

    for (int t = 0; t < N_STEP; t++) {
        const __half* hsrc = (t & 1) ? p_hb : p_ha;
        __half*       hdst = (t & 1) ? p_ha : p_hb;
        fused_step<<<dim3(HID / FBU, BS / FBM), 256, FUSED_SMEM_BYTES>>>(hsrc, hdst, b_hh);
        out_head<<<BS, 128>>>(W_out, b_out, recon, t);
    }
}